// round 4
// baseline (speedup 1.0000x reference)
#include <cuda_runtime.h>
#include <cuda_bf16.h>
#include <cstdint>

// TensorDLT closed-form solve for fixed source corners
// (0,0),(127,0),(127,127),(0,127). 8 fp32 in -> 9 fp32 out per element.
//
//   h2 = u1', h5 = v1'
//   a_i = (u_i'-u1')/127, c_i = (v1'-v_i')/127
//   2x2:  (u2'-u3') h6 + (u4'-u3') h7 = a3-a2-a4
//         (v3'-v2') h6 + (v3'-v4') h7 = c3-c2-c4
//   h0 = u2' h6 + a2, h1 = u4' h7 + a4, h3 = v2' h6 - c2, h4 = v4' h7 - c4
//
// R4: warp-local SMEM staging (no block barrier, no TMA drain) + rcp.approx
// to shorten the per-CTA critical chain.

#define BLOCK 256

__device__ __forceinline__ float frcp_approx(float x) {
    float r;
    asm("rcp.approx.f32 %0, %1;" : "=f"(r) : "f"(x));
    return r;
}

__global__ void __launch_bounds__(BLOCK) tensor_dlt_kernel(
    const float* __restrict__ offset,  // [B, 8]
    float* __restrict__ out,           // [B, 9]
    int B)
{
    // One 288-float (1152 B) slice per warp, 16B-aligned.
    __shared__ __align__(16) float s[BLOCK * 9];

    const int warp = threadIdx.x >> 5;
    const int lane = threadIdx.x & 31;
    const int b = blockIdx.x * BLOCK + threadIdx.x;

    float* slice = s + warp * 288;

    if (b < B) {
        const float4* p = reinterpret_cast<const float4*>(offset) + (size_t)b * 2;
        const float4 o0 = p[0];
        const float4 o1 = p[1];

        const float up1 =   0.0f + 32.0f * o0.x;
        const float vp1 =   0.0f + 32.0f * o0.y;
        const float up2 = 127.0f + 32.0f * o0.z;
        const float vp2 =   0.0f + 32.0f * o0.w;
        const float up3 = 127.0f + 32.0f * o1.x;
        const float vp3 = 127.0f + 32.0f * o1.y;
        const float up4 =   0.0f + 32.0f * o1.z;
        const float vp4 = 127.0f + 32.0f * o1.w;

        const float inv127 = 1.0f / 127.0f;
        const float a2 = (up2 - up1) * inv127;
        const float a3 = (up3 - up1) * inv127;
        const float a4 = (up4 - up1) * inv127;
        const float c2 = (vp1 - vp2) * inv127;
        const float c3 = (vp1 - vp3) * inv127;
        const float c4 = (vp1 - vp4) * inv127;

        const float m00 = up2 - up3;
        const float m01 = up4 - up3;
        const float m10 = vp3 - vp2;
        const float m11 = vp3 - vp4;
        const float r0 = a3 - a2 - a4;
        const float r1 = c3 - c2 - c4;

        // det ~ +127^2 for |perturbation|<=32 -> well-conditioned; approx
        // reciprocal (rel err ~1e-7) is far inside the 1e-3 budget.
        const float invdet = frcp_approx(m00 * m11 - m01 * m10);
        const float h6 = (r0 * m11 - m01 * r1) * invdet;
        const float h7 = (m00 * r1 - r0 * m10) * invdet;

        // stride-9 STS: bank = (9*lane + c) mod 32, distinct per lane
        float* row = slice + lane * 9;
        row[0] = up2 * h6 + a2;
        row[1] = up4 * h7 + a4;
        row[2] = up1;
        row[3] = vp2 * h6 - c2;
        row[4] = vp4 * h7 - c4;
        row[5] = vp1;
        row[6] = h6;
        row[7] = h7;
        row[8] = 1.0f;
    }
    __syncwarp();

    // Warp-coalesced flush: 72 float4 per warp slice.
    const int warpBase = blockIdx.x * BLOCK + warp * 32;
    const int valid = min(32, B - warpBase);

    if (valid == 32) {
        const float4* s4 = reinterpret_cast<const float4*>(slice);
        float4* d4 = reinterpret_cast<float4*>(out + (size_t)warpBase * 9);
        d4[lane]      = s4[lane];
        d4[lane + 32] = s4[lane + 32];
        if (lane < 8)
            d4[lane + 64] = s4[lane + 64];
    } else if (valid > 0) {
        float* dst = out + (size_t)warpBase * 9;
        const int n = valid * 9;
        for (int i = lane; i < n; i += 32)
            dst[i] = slice[i];
    }
}

extern "C" void kernel_launch(void* const* d_in, const int* in_sizes, int n_in,
                              void* d_out, int out_size)
{
    const float* offset = (const float*)d_in[0];
    float* out = (float*)d_out;
    const int B = in_sizes[0] / 8;
    const int grid = (B + BLOCK - 1) / BLOCK;
    tensor_dlt_kernel<<<grid, BLOCK>>>(offset, out, B);
}

// round 5
// speedup vs baseline: 1.0333x; 1.0333x over previous
#include <cuda_runtime.h>
#include <cuda_bf16.h>
#include <cstdint>

// TensorDLT closed-form solve for fixed source corners
// (0,0),(127,0),(127,127),(0,127). 8 fp32 in -> 9 fp32 out per element.
//
//   h2 = u1', h5 = v1'
//   a_i = (u_i'-u1')/127, c_i = (v1'-v_i')/127
//   2x2:  (u2'-u3') h6 + (u4'-u3') h7 = a3-a2-a4
//         (v3'-v2') h6 + (v3'-v4') h7 = c3-c2-c4
//   h0 = u2' h6 + a2, h1 = u4' h7 + a4, h3 = v2' h6 - c2, h4 = v4' h7 - c4
//
// R5: fully async-bulk memory path. Input: one cp.async.bulk (8 KB) per CTA
// into SMEM + mbarrier wait. Output: STS staging + one cp.async.bulk store.
// The SM never issues a global load/store for the main path; DRAM latency is
// absorbed by the async engines with 8 CTAs x 8KB in flight per SM.

#define BLOCK 256

__device__ __forceinline__ uint32_t smem_u32(const void* p) {
    uint32_t a;
    asm("{ .reg .u64 t; cvta.to.shared.u64 t, %1; cvt.u32.u64 %0, t; }"
        : "=r"(a) : "l"(p));
    return a;
}

__device__ __forceinline__ float frcp_approx(float x) {
    float r;
    asm("rcp.approx.f32 %0, %1;" : "=f"(r) : "f"(x));
    return r;
}

__device__ __forceinline__ void mbar_wait(uint32_t mbar, uint32_t parity) {
    asm volatile(
        "{\n\t"
        ".reg .pred P;\n\t"
        "WAIT_%=: \n\t"
        "mbarrier.try_wait.parity.acquire.cta.shared::cta.b64 P, [%0], %1, 0x989680;\n\t"
        "@P bra.uni DONE_%=;\n\t"
        "bra.uni WAIT_%=;\n\t"
        "DONE_%=: \n\t"
        "}"
        :: "r"(mbar), "r"(parity) : "memory");
}

__global__ void __launch_bounds__(BLOCK) tensor_dlt_kernel(
    const float* __restrict__ offset,  // [B, 8]
    float* __restrict__ out,           // [B, 9]
    int B)
{
    __shared__ __align__(16) float sin_[BLOCK * 8];   // 8192 B
    __shared__ __align__(16) float sout[BLOCK * 9];   // 9216 B
    __shared__ __align__(8)  uint64_t mbar;

    const int base = blockIdx.x * BLOCK;
    const bool full = (base + BLOCK <= B);
    const uint32_t mb = smem_u32(&mbar);

    float4 o0, o1;

    if (full) {
        if (threadIdx.x == 0)
            asm volatile("mbarrier.init.shared.b64 [%0], 1;" :: "r"(mb) : "memory");
        __syncthreads();
        if (threadIdx.x == 0) {
            asm volatile("mbarrier.arrive.expect_tx.shared.b64 _, [%0], %1;"
                         :: "r"(mb), "n"(BLOCK * 8 * 4) : "memory");
            asm volatile(
                "cp.async.bulk.shared::cluster.global.mbarrier::complete_tx::bytes "
                "[%0], [%1], %2, [%3];"
                :: "r"(smem_u32(sin_)),
                   "l"(offset + (size_t)base * 8),
                   "n"(BLOCK * 8 * 4),
                   "r"(mb)
                : "memory");
        }
        mbar_wait(mb, 0);

        const float4* pin = reinterpret_cast<const float4*>(sin_) + threadIdx.x * 2;
        o0 = pin[0];
        o1 = pin[1];
    } else {
        // Tail fallback: per-thread global loads.
        const int b = base + threadIdx.x;
        if (b < B) {
            const float4* p = reinterpret_cast<const float4*>(offset) + (size_t)b * 2;
            o0 = p[0];
            o1 = p[1];
        } else {
            o0 = make_float4(0.f, 0.f, 0.f, 0.f);
            o1 = make_float4(0.f, 0.f, 0.f, 0.f);
        }
    }

    if (full || base + threadIdx.x < B) {
        const float up1 =   0.0f + 32.0f * o0.x;
        const float vp1 =   0.0f + 32.0f * o0.y;
        const float up2 = 127.0f + 32.0f * o0.z;
        const float vp2 =   0.0f + 32.0f * o0.w;
        const float up3 = 127.0f + 32.0f * o1.x;
        const float vp3 = 127.0f + 32.0f * o1.y;
        const float up4 =   0.0f + 32.0f * o1.z;
        const float vp4 = 127.0f + 32.0f * o1.w;

        const float inv127 = 1.0f / 127.0f;
        const float a2 = (up2 - up1) * inv127;
        const float a3 = (up3 - up1) * inv127;
        const float a4 = (up4 - up1) * inv127;
        const float c2 = (vp1 - vp2) * inv127;
        const float c3 = (vp1 - vp3) * inv127;
        const float c4 = (vp1 - vp4) * inv127;

        const float m00 = up2 - up3;
        const float m01 = up4 - up3;
        const float m10 = vp3 - vp2;
        const float m11 = vp3 - vp4;
        const float r0 = a3 - a2 - a4;
        const float r1 = c3 - c2 - c4;

        // det ~ +127^2 for |perturbation|<=32 -> well-conditioned.
        const float invdet = frcp_approx(m00 * m11 - m01 * m10);
        const float h6 = (r0 * m11 - m01 * r1) * invdet;
        const float h7 = (m00 * r1 - r0 * m10) * invdet;

        // stride-9 STS: gcd(9,32)=1 -> bank-conflict-free
        float* row = sout + threadIdx.x * 9;
        row[0] = up2 * h6 + a2;
        row[1] = up4 * h7 + a4;
        row[2] = up1;
        row[3] = vp2 * h6 - c2;
        row[4] = vp4 * h7 - c4;
        row[5] = vp1;
        row[6] = h6;
        row[7] = h7;
        row[8] = 1.0f;
    }
    __syncthreads();

    float* dst = out + (size_t)base * 9;

    if (full) {
        // One async bulk store per block: 9216 B, dst 16B-aligned.
        if (threadIdx.x == 0) {
            asm volatile("fence.proxy.async.shared::cta;" ::: "memory");
            asm volatile(
                "cp.async.bulk.global.shared::cta.bulk_group [%0], [%1], %2;"
                :: "l"(dst), "r"(smem_u32(sout)), "n"(BLOCK * 9 * 4)
                : "memory");
            asm volatile("cp.async.bulk.commit_group;" ::: "memory");
            // Must complete before CTA exit frees SMEM.
            asm volatile("cp.async.bulk.wait_group.read 0;" ::: "memory");
        }
    } else {
        const int valid = min(BLOCK, B - base);
        if (valid > 0) {
            const int n = valid * 9;
            for (int i = threadIdx.x; i < n; i += BLOCK)
                dst[i] = sout[i];
        }
    }
}

extern "C" void kernel_launch(void* const* d_in, const int* in_sizes, int n_in,
                              void* d_out, int out_size)
{
    const float* offset = (const float*)d_in[0];
    float* out = (float*)d_out;
    const int B = in_sizes[0] / 8;
    const int grid = (B + BLOCK - 1) / BLOCK;
    tensor_dlt_kernel<<<grid, BLOCK>>>(offset, out, B);
}